// round 5
// baseline (speedup 1.0000x reference)
#include <cuda_runtime.h>
#include <cuda_bf16.h>
#include <cstdint>

#define NUM_KNOTS 30
#define NI (NUM_KNOTS - 1)   // 29 intervals
#define PCHIP_EPS 1e-12f
#define REP 8                // 8-way table replication -> conflict-free LDS.128

// ---------------------------------------------------------------------------
// Fused kernel:
//   1. Warp 0 computes PCHIP slopes + per-interval cubic coefficients
//      (p(t) = c0 + c1 t + c2 t^2 + c3 t^3, t in [0,1]) warp-parallel via
//      shuffles, writes an 8-way bank-replicated float4 table to smem.
//   2. All threads grid-stride, 2 float4 per iteration with both LDG.128
//      issued back-to-back (MLP=2) before the dependent LDS/FMA chain.
//      Full occupancy (8 blocks/SM) is kept — no cross-iteration pipeline
//      state, no register bloat.
//
// LDS.128 conflicts: lane L reads tbl[idx_L*8 + (L&7)] -> bank 4*(L&7)+w,
// independent of idx: every 8-lane phase covers all 32 banks once ->
// always the minimal 4 wavefronts.
// ---------------------------------------------------------------------------

__device__ __forceinline__ float eval_one(float xv, float k0, float kK,
                                          float scale,
                                          const float4* __restrict__ tl) {
    float xc = fminf(fmaxf(xv, k0), kK);
    float u = (xc - k0) * scale;          // in [0, NI]
    int idx = (int)u;                     // trunc == floor (u >= 0)
    idx = min(idx, NI - 1);
    float t = u - (float)idx;
    float4 c = tl[idx * REP];             // one LDS.128, conflict-free
    return fmaf(fmaf(fmaf(c.w, t, c.z), t, c.y), t, c.x);
}

__device__ __forceinline__ float4 eval_vec(float4 v, float k0, float kK,
                                           float scale,
                                           const float4* __restrict__ tl) {
    float4 r;
    r.x = eval_one(v.x, k0, kK, scale, tl);
    r.y = eval_one(v.y, k0, kK, scale, tl);
    r.z = eval_one(v.z, k0, kK, scale, tl);
    r.w = eval_one(v.w, k0, kK, scale, tl);
    return r;
}

__global__ void __launch_bounds__(256)
spline_fused_kernel(const float4* __restrict__ x4, float4* __restrict__ out4,
                    int n4, int n, const float* __restrict__ x,
                    float* __restrict__ out,
                    const float* __restrict__ knots,
                    const float* __restrict__ coeffs) {
    __shared__ float4 tbl[NI * REP];      // 3712 bytes
    __shared__ float s_par[3];            // k0, kK, scale

    const int tid = threadIdx.x;

    // ---- warp-parallel PCHIP prep (warp 0 only) ----
    if (tid < 32) {
        const unsigned FULL = 0xFFFFFFFFu;
        const int lane = tid;

        float k_i = (lane < NUM_KNOTS) ? knots[lane]  : 0.0f;
        float c_i = (lane < NUM_KNOTS) ? coeffs[lane] : 0.0f;
        float k_ip1 = __shfl_down_sync(FULL, k_i, 1);
        float c_ip1 = __shfl_down_sync(FULL, c_i, 1);

        float h = 0.0f, delta = 0.0f;
        if (lane < NI) {
            h = k_ip1 - k_i;
            delta = (c_ip1 - c_i) / (h + PCHIP_EPS);
        }
        float h_m1     = __shfl_up_sync(FULL, h, 1);
        float delta_m1 = __shfl_up_sync(FULL, delta, 1);
        float h_p1     = __shfl_down_sync(FULL, h, 1);
        float delta_p1 = __shfl_down_sync(FULL, delta, 1);

        float d = 0.0f;
        if (lane >= 1 && lane <= NI - 1) {
            // interior knot slope (weighted harmonic mean, 0 at sign change)
            float w1 = 2.0f * h + h_m1;
            float w2 = h + 2.0f * h_m1;
            float di = (w1 + w2) / (w1 / (delta_m1 + PCHIP_EPS) +
                                    w2 / (delta + PCHIP_EPS));
            d = (delta_m1 * delta > 0.0f) ? di : 0.0f;
        }
        if (lane == 0) {
            // left endpoint + limiter (zero-check first, then 3x clamp)
            float d0 = ((2.0f * h + h_p1) * delta - h * delta_p1) /
                       (h + h_p1 + PCHIP_EPS);
            if (d0 * delta <= 0.0f) d0 = 0.0f;
            else if (fabsf(d0) > 3.0f * fabsf(delta)) d0 = 3.0f * delta;
            d = d0;
        }
        float dN = 0.0f;
        if (lane == NI - 1) {
            // right endpoint computed on lane 28 (has h28,h27,delta28,delta27)
            dN = ((2.0f * h + h_m1) * delta - h * delta_m1) /
                 (h + h_m1 + PCHIP_EPS);
            if (dN * delta <= 0.0f) dN = 0.0f;
            else if (fabsf(dN) > 3.0f * fabsf(delta)) dN = 3.0f * delta;
        }
        float d_p1 = __shfl_down_sync(FULL, d, 1);   // d_{i+1}
        if (lane == NI - 1) d_p1 = dN;

        if (lane < NI) {
            float y0 = c_i, y1 = c_ip1;
            float hd0 = h * d;
            float hd1 = h * d_p1;
            float4 c;
            c.x = y0;
            c.y = hd0;
            c.z = -3.0f * y0 - 2.0f * hd0 + 3.0f * y1 - hd1;
            c.w =  2.0f * y0 +        hd0 - 2.0f * y1 + hd1;
            #pragma unroll
            for (int r = 0; r < REP; r++) tbl[lane * REP + r] = c;
        }
        if (lane == 0) {
            float k0 = knots[0];
            float kK = knots[NUM_KNOTS - 1];
            s_par[0] = k0;
            s_par[1] = kK;
            s_par[2] = (float)NI / (kK - k0);
        }
    }
    __syncthreads();

    const float k0 = s_par[0];
    const float kK = s_par[1];
    const float scale = s_par[2];
    const float4* tl = tbl + (tid & (REP - 1));

    const int stride = gridDim.x * blockDim.x;
    const int gid = blockIdx.x * blockDim.x + tid;

    // ---- 2-wide grid-stride: both loads issue before the compute chain ----
    for (int i = gid; i < n4; i += 2 * stride) {
        int i2 = i + stride;
        float4 a = __ldcs(&x4[i]);
        float4 b;
        bool vb = (i2 < n4);
        if (vb) b = __ldcs(&x4[i2]);

        __stcs(&out4[i], eval_vec(a, k0, kK, scale, tl));
        if (vb) __stcs(&out4[i2], eval_vec(b, k0, kK, scale, tl));
    }

    // scalar tail (n not multiple of 4)
    int tail_start = n4 * 4;
    for (int j = tail_start + gid; j < n; j += stride) {
        out[j] = eval_one(__ldcs(&x[j]), k0, kK, scale, tl);
    }
}

// ---------------------------------------------------------------------------
extern "C" void kernel_launch(void* const* d_in, const int* in_sizes, int n_in,
                              void* d_out, int out_size) {
    const float* x      = (const float*)d_in[0];
    const float* knots  = (const float*)d_in[1];
    const float* coeffs = (const float*)d_in[2];
    float* out = (float*)d_out;

    int n = out_size;
    int n4 = n / 4;

    const int threads = 256;
    int blocks = 148 * 8;   // full wave, 8 blocks/SM (R2's winning occupancy)
    int maxb = (n4 + threads - 1) / threads;
    if (maxb < 1) maxb = 1;
    if (blocks > maxb) blocks = maxb;

    spline_fused_kernel<<<blocks, threads>>>((const float4*)x, (float4*)out,
                                             n4, n, x, out, knots, coeffs);
}

// round 6
// speedup vs baseline: 1.1564x; 1.1564x over previous
#include <cuda_runtime.h>
#include <cuda_bf16.h>
#include <cstdint>

#define NUM_KNOTS 30
#define NI (NUM_KNOTS - 1)   // 29 intervals
#define PCHIP_EPS 1e-12f
#define REP 8                // 8-way table replication -> conflict-free LDS.128

// ---------------------------------------------------------------------------
// Fused kernel (R2 shape + branch-free 2-wide main loop):
//   1. Warp 0 computes PCHIP slopes + per-interval cubic coefficients
//      (p(t) = c0 + c1 t + c2 t^2 + c3 t^3, t in [0,1]) warp-parallel via
//      shuffles, writes an 8-way bank-replicated float4 table to smem.
//   2. Main loop: UNCONDITIONAL pair of LDG.128 (batched, MLP=2) ->
//      eval -> pair of STG.128. No predication/branches in the body
//      (R5 showed guarded loads collapse occupancy/issue).
//   3. Remainder (at most one element slot per thread) handled after.
//
// LDS.128 conflicts: lane L reads tbl[idx_L*8 + (L&7)] -> bank 4*(L&7)+w,
// independent of idx: every 8-lane phase covers all 32 banks once ->
// always the minimal 4 wavefronts.
// ---------------------------------------------------------------------------

__device__ __forceinline__ float eval_one(float xv, float k0, float kK,
                                          float scale,
                                          const float4* __restrict__ tl) {
    float xc = fminf(fmaxf(xv, k0), kK);
    float u = (xc - k0) * scale;          // in [0, NI]
    int idx = (int)u;                     // trunc == floor (u >= 0)
    idx = min(idx, NI - 1);
    float t = u - (float)idx;
    float4 c = tl[idx * REP];             // one LDS.128, conflict-free
    return fmaf(fmaf(fmaf(c.w, t, c.z), t, c.y), t, c.x);
}

__device__ __forceinline__ float4 eval_vec(float4 v, float k0, float kK,
                                           float scale,
                                           const float4* __restrict__ tl) {
    float4 r;
    r.x = eval_one(v.x, k0, kK, scale, tl);
    r.y = eval_one(v.y, k0, kK, scale, tl);
    r.z = eval_one(v.z, k0, kK, scale, tl);
    r.w = eval_one(v.w, k0, kK, scale, tl);
    return r;
}

__global__ void __launch_bounds__(256)
spline_fused_kernel(const float4* __restrict__ x4, float4* __restrict__ out4,
                    int n4, int n, const float* __restrict__ x,
                    float* __restrict__ out,
                    const float* __restrict__ knots,
                    const float* __restrict__ coeffs) {
    __shared__ float4 tbl[NI * REP];      // 3712 bytes
    __shared__ float s_par[3];            // k0, kK, scale

    const int tid = threadIdx.x;

    // ---- warp-parallel PCHIP prep (warp 0 only) ----
    if (tid < 32) {
        const unsigned FULL = 0xFFFFFFFFu;
        const int lane = tid;

        float k_i = (lane < NUM_KNOTS) ? knots[lane]  : 0.0f;
        float c_i = (lane < NUM_KNOTS) ? coeffs[lane] : 0.0f;
        float k_ip1 = __shfl_down_sync(FULL, k_i, 1);
        float c_ip1 = __shfl_down_sync(FULL, c_i, 1);

        float h = 0.0f, delta = 0.0f;
        if (lane < NI) {
            h = k_ip1 - k_i;
            delta = (c_ip1 - c_i) / (h + PCHIP_EPS);
        }
        float h_m1     = __shfl_up_sync(FULL, h, 1);
        float delta_m1 = __shfl_up_sync(FULL, delta, 1);
        float h_p1     = __shfl_down_sync(FULL, h, 1);
        float delta_p1 = __shfl_down_sync(FULL, delta, 1);

        float d = 0.0f;
        if (lane >= 1 && lane <= NI - 1) {
            // interior knot slope (weighted harmonic mean, 0 at sign change)
            float w1 = 2.0f * h + h_m1;
            float w2 = h + 2.0f * h_m1;
            float di = (w1 + w2) / (w1 / (delta_m1 + PCHIP_EPS) +
                                    w2 / (delta + PCHIP_EPS));
            d = (delta_m1 * delta > 0.0f) ? di : 0.0f;
        }
        if (lane == 0) {
            // left endpoint + limiter (zero-check first, then 3x clamp)
            float d0 = ((2.0f * h + h_p1) * delta - h * delta_p1) /
                       (h + h_p1 + PCHIP_EPS);
            if (d0 * delta <= 0.0f) d0 = 0.0f;
            else if (fabsf(d0) > 3.0f * fabsf(delta)) d0 = 3.0f * delta;
            d = d0;
        }
        float dN = 0.0f;
        if (lane == NI - 1) {
            // right endpoint computed on lane 28 (has h28,h27,delta28,delta27)
            dN = ((2.0f * h + h_m1) * delta - h * delta_m1) /
                 (h + h_m1 + PCHIP_EPS);
            if (dN * delta <= 0.0f) dN = 0.0f;
            else if (fabsf(dN) > 3.0f * fabsf(delta)) dN = 3.0f * delta;
        }
        float d_p1 = __shfl_down_sync(FULL, d, 1);   // d_{i+1}
        if (lane == NI - 1) d_p1 = dN;

        if (lane < NI) {
            float y0 = c_i, y1 = c_ip1;
            float hd0 = h * d;
            float hd1 = h * d_p1;
            float4 c;
            c.x = y0;
            c.y = hd0;
            c.z = -3.0f * y0 - 2.0f * hd0 + 3.0f * y1 - hd1;
            c.w =  2.0f * y0 +        hd0 - 2.0f * y1 + hd1;
            #pragma unroll
            for (int r = 0; r < REP; r++) tbl[lane * REP + r] = c;
        }
        if (lane == 0) {
            float k0 = knots[0];
            float kK = knots[NUM_KNOTS - 1];
            s_par[0] = k0;
            s_par[1] = kK;
            s_par[2] = (float)NI / (kK - k0);
        }
    }
    __syncthreads();

    const float k0 = s_par[0];
    const float kK = s_par[1];
    const float scale = s_par[2];
    const float4* tl = tbl + (tid & (REP - 1));

    const int stride = gridDim.x * blockDim.x;
    int i = blockIdx.x * blockDim.x + tid;

    // ---- branch-free 2-wide main loop: both loads unconditional ----
    for (; i + stride < n4; i += 2 * stride) {
        float4 a = __ldcs(&x4[i]);
        float4 b = __ldcs(&x4[i + stride]);
        __stcs(&out4[i],          eval_vec(a, k0, kK, scale, tl));
        __stcs(&out4[i + stride], eval_vec(b, k0, kK, scale, tl));
    }
    // at most one leftover float4 per thread
    if (i < n4) {
        float4 a = __ldcs(&x4[i]);
        __stcs(&out4[i], eval_vec(a, k0, kK, scale, tl));
    }

    // scalar tail (n not multiple of 4)
    int tail_start = n4 * 4;
    int gid = blockIdx.x * blockDim.x + tid;
    for (int j = tail_start + gid; j < n; j += stride) {
        out[j] = eval_one(__ldcs(&x[j]), k0, kK, scale, tl);
    }
}

// ---------------------------------------------------------------------------
extern "C" void kernel_launch(void* const* d_in, const int* in_sizes, int n_in,
                              void* d_out, int out_size) {
    const float* x      = (const float*)d_in[0];
    const float* knots  = (const float*)d_in[1];
    const float* coeffs = (const float*)d_in[2];
    float* out = (float*)d_out;

    int n = out_size;
    int n4 = n / 4;

    const int threads = 256;
    int blocks = 148 * 8;   // full wave, 8 blocks/SM (R2's winning occupancy)
    int maxb = (n4 + threads - 1) / threads;
    if (maxb < 1) maxb = 1;
    if (blocks > maxb) blocks = maxb;

    spline_fused_kernel<<<blocks, threads>>>((const float4*)x, (float4*)out,
                                             n4, n, x, out, knots, coeffs);
}

// round 7
// speedup vs baseline: 1.2529x; 1.0834x over previous
#include <cuda_runtime.h>
#include <cuda_bf16.h>
#include <cstdint>

#define NUM_KNOTS 30
#define NI (NUM_KNOTS - 1)   // 29 intervals
#define PCHIP_EPS 1e-12f
#define REP 8                // table replication factor (8 copies -> conflict-free LDS.128)

// ---------------------------------------------------------------------------
// Fused kernel (confirmed-best R2 configuration):
//   1. Warp 0 computes PCHIP slopes + per-interval cubic coefficients
//      (p(t) = c0 + c1 t + c2 t^2 + c3 t^3, t in [0,1]) warp-parallel via
//      shuffles, and writes an 8-way bank-replicated float4 table to smem.
//   2. All threads stream-evaluate with one LDS.128 per element,
//      simple 1-wide grid-stride loop at full occupancy (8 blocks/SM).
//
// LDS.128 conflict analysis: lane L reads tbl[idx_L*8 + (L&7)].
// Word address = idx_L*32 + (L&7)*4 + w  ->  bank = 4*(L&7)+w (mod 32),
// independent of idx. Each 8-lane phase covers all 32 banks exactly once ->
// always the 4-wavefront (512B) minimum, regardless of the random idx.
// ---------------------------------------------------------------------------

__device__ __forceinline__ float eval_one(float xv, float k0, float kK,
                                          float scale,
                                          const float4* __restrict__ tl) {
    float xc = fminf(fmaxf(xv, k0), kK);
    float u = (xc - k0) * scale;          // in [0, NI]
    int idx = (int)u;                     // trunc == floor (u >= 0)
    idx = min(idx, NI - 1);
    float t = u - (float)idx;
    float4 c = tl[idx * REP];             // one LDS.128
    return fmaf(fmaf(fmaf(c.w, t, c.z), t, c.y), t, c.x);
}

__global__ void __launch_bounds__(256)
spline_fused_kernel(const float4* __restrict__ x4, float4* __restrict__ out4,
                    int n4, int n, const float* __restrict__ x,
                    float* __restrict__ out,
                    const float* __restrict__ knots,
                    const float* __restrict__ coeffs) {
    __shared__ float4 tbl[NI * REP];      // 3712 bytes
    __shared__ float s_par[3];            // k0, kK, scale

    const int tid = threadIdx.x;

    // ---- warp-parallel PCHIP prep (warp 0 only) ----
    if (tid < 32) {
        const unsigned FULL = 0xFFFFFFFFu;
        const int lane = tid;

        float k_i = (lane < NUM_KNOTS) ? knots[lane]  : 0.0f;
        float c_i = (lane < NUM_KNOTS) ? coeffs[lane] : 0.0f;
        float k_ip1 = __shfl_down_sync(FULL, k_i, 1);
        float c_ip1 = __shfl_down_sync(FULL, c_i, 1);

        float h = 0.0f, delta = 0.0f;
        if (lane < NI) {
            h = k_ip1 - k_i;
            delta = (c_ip1 - c_i) / (h + PCHIP_EPS);
        }
        float h_m1     = __shfl_up_sync(FULL, h, 1);
        float delta_m1 = __shfl_up_sync(FULL, delta, 1);
        float h_p1     = __shfl_down_sync(FULL, h, 1);
        float delta_p1 = __shfl_down_sync(FULL, delta, 1);

        float d = 0.0f;
        if (lane >= 1 && lane <= NI - 1) {
            // interior knot slope (weighted harmonic mean, 0 at sign change)
            float w1 = 2.0f * h + h_m1;
            float w2 = h + 2.0f * h_m1;
            float di = (w1 + w2) / (w1 / (delta_m1 + PCHIP_EPS) +
                                    w2 / (delta + PCHIP_EPS));
            d = (delta_m1 * delta > 0.0f) ? di : 0.0f;
        }
        if (lane == 0) {
            // left endpoint + limiter (zero-check first, then 3x clamp)
            float d0 = ((2.0f * h + h_p1) * delta - h * delta_p1) /
                       (h + h_p1 + PCHIP_EPS);
            if (d0 * delta <= 0.0f) d0 = 0.0f;
            else if (fabsf(d0) > 3.0f * fabsf(delta)) d0 = 3.0f * delta;
            d = d0;
        }
        float dN = 0.0f;
        if (lane == NI - 1) {
            // right endpoint computed on lane 28 (has h28,h27,delta28,delta27)
            dN = ((2.0f * h + h_m1) * delta - h * delta_m1) /
                 (h + h_m1 + PCHIP_EPS);
            if (dN * delta <= 0.0f) dN = 0.0f;
            else if (fabsf(dN) > 3.0f * fabsf(delta)) dN = 3.0f * delta;
        }
        float d_p1 = __shfl_down_sync(FULL, d, 1);   // d_{i+1}
        if (lane == NI - 1) d_p1 = dN;

        if (lane < NI) {
            float y0 = c_i, y1 = c_ip1;
            float hd0 = h * d;
            float hd1 = h * d_p1;
            float4 c;
            c.x = y0;
            c.y = hd0;
            c.z = -3.0f * y0 - 2.0f * hd0 + 3.0f * y1 - hd1;
            c.w =  2.0f * y0 +        hd0 - 2.0f * y1 + hd1;
            #pragma unroll
            for (int r = 0; r < REP; r++) tbl[lane * REP + r] = c;
        }
        if (lane == 0) {
            float k0 = knots[0];
            float kK = knots[NUM_KNOTS - 1];
            s_par[0] = k0;
            s_par[1] = kK;
            s_par[2] = (float)NI / (kK - k0);
        }
    }
    __syncthreads();

    const float k0 = s_par[0];
    const float kK = s_par[1];
    const float scale = s_par[2];
    const float4* tl = tbl + (tid & (REP - 1));

    int stride = gridDim.x * blockDim.x;
    int gid = blockIdx.x * blockDim.x + tid;

    for (int i = gid; i < n4; i += stride) {
        float4 v = __ldcs(&x4[i]);
        float4 r;
        r.x = eval_one(v.x, k0, kK, scale, tl);
        r.y = eval_one(v.y, k0, kK, scale, tl);
        r.z = eval_one(v.z, k0, kK, scale, tl);
        r.w = eval_one(v.w, k0, kK, scale, tl);
        __stcs(&out4[i], r);
    }

    // scalar tail (n not multiple of 4)
    int tail_start = n4 * 4;
    for (int i = tail_start + gid; i < n; i += stride) {
        out[i] = eval_one(__ldcs(&x[i]), k0, kK, scale, tl);
    }
}

// ---------------------------------------------------------------------------
extern "C" void kernel_launch(void* const* d_in, const int* in_sizes, int n_in,
                              void* d_out, int out_size) {
    const float* x      = (const float*)d_in[0];
    const float* knots  = (const float*)d_in[1];
    const float* coeffs = (const float*)d_in[2];
    float* out = (float*)d_out;

    int n = out_size;
    int n4 = n / 4;

    const int threads = 256;
    int blocks = 148 * 8;   // one full wave at 8 blocks/SM (2048 thr, 32 regs)
    int maxb = (n4 + threads - 1) / threads;
    if (maxb < 1) maxb = 1;
    if (blocks > maxb) blocks = maxb;

    spline_fused_kernel<<<blocks, threads>>>((const float4*)x, (float4*)out,
                                             n4, n, x, out, knots, coeffs);
}